// round 4
// baseline (speedup 1.0000x reference)
#include <cuda_runtime.h>
#include <cuda_bf16.h>
#include <cuda_fp16.h>
#include <cuda_fp8.h>
#include <cstdint>

#define BB 64
#define TT 512
#define SS 4
#define HH 512
#define VV 10000
#define HALFH 256

// ---------------- device scratch ----------------
__device__ float g_lse[SS * HH];
__device__ float g_leT[(size_t)SS * VV * HH];          // [s][v][h]
__device__ float g_E[(size_t)BB * TT * HH];            // exp(em - smax)
__device__ float g_smax[BB * TT];
__device__ unsigned char g_P8[HH * HH];                // e4m3(P*256) (used rows: (j&128)!=0)
__device__ __half g_Ph[(size_t)HH * HH];               // half(P)     (used rows: (j&128)==0)
__device__ float g_corr[HH];                           // per-row quant row-sum correction
__device__ int g_is64;

// ---------------- helpers ----------------
__device__ __forceinline__ float warp_sum(float v) {
    #pragma unroll
    for (int o = 16; o; o >>= 1) v += __shfl_xor_sync(0xffffffffu, v, o);
    return v;
}
__device__ __forceinline__ float warp_max(float v) {
    #pragma unroll
    for (int o = 16; o; o >>= 1) v = fmaxf(v, __shfl_xor_sync(0xffffffffu, v, o));
    return v;
}
__device__ __forceinline__ uint32_t smem_u32(const void* p) {
    uint32_t a;
    asm("{ .reg .u64 t; cvta.to.shared.u64 t, %1; cvt.u32.u64 %0, t; }" : "=r"(a) : "l"(p));
    return a;
}
__device__ __forceinline__ __half2 u32_h2(unsigned u) {
    __half2 h;
    *reinterpret_cast<unsigned*>(&h) = u;
    return h;
}
// sign-free e4m3 -> half via bit shift: half_bits = byte<<7, value = e4m3 * 2^-8.
// P stored as e4m3(P*256) => dequant yields exactly P (scales cancel).
__device__ __forceinline__ __half2 fp8lo(unsigned q) { return u32_h2((q & 0x00ff00ffu) << 7); }   // (b0,b2)
__device__ __forceinline__ __half2 fp8hi(unsigned q) { return u32_h2((q >> 1) & 0x7f807f80u); }   // (b1,b3)

__device__ __forceinline__ void mbar_init(uint32_t m, unsigned cnt) {
    asm volatile("mbarrier.init.shared.b64 [%0], %1;" :: "r"(m), "r"(cnt) : "memory");
}
__device__ __forceinline__ void mbar_arrive_remote(uint32_t m_local, unsigned peer) {
    asm volatile("{\n\t.reg .b32 r;\n\t"
                 "mapa.shared::cluster.u32 r, %0, %1;\n\t"
                 "mbarrier.arrive.release.cluster.shared::cluster.b64 _, [r];\n\t}"
                 :: "r"(m_local), "r"(peer) : "memory");
}
__device__ __forceinline__ void st_remote_f32(uint32_t a_local, unsigned peer, float v) {
    asm volatile("{\n\t.reg .b32 r;\n\t"
                 "mapa.shared::cluster.u32 r, %0, %1;\n\t"
                 "st.shared::cluster.f32 [r], %2;\n\t}"
                 :: "r"(a_local), "r"(peer), "f"(v) : "memory");
}
__device__ __forceinline__ void mbar_wait(uint32_t m, unsigned parity) {
    asm volatile("{\n\t.reg .pred P;\n\t"
                 "WL_%=:\n\t"
                 "mbarrier.try_wait.parity.acquire.cluster.shared::cta.b64 P, [%0], %1, 0x989680;\n\t"
                 "@P bra WD_%=;\n\t"
                 "bra WL_%=;\n\t"
                 "WD_%=:\n\t}"
                 :: "r"(m), "r"(parity) : "memory");
}
#define CLUSTER_SYNC_() do { \
    asm volatile("barrier.cluster.arrive.aligned;" ::: "memory"); \
    asm volatile("barrier.cluster.wait.aligned;" ::: "memory"); } while (0)

// ---------------- kernel 0: detect int64 vs int32 ----------------
__global__ void detect_kernel(const int* obs32) {
    if (threadIdx.x == 0) {
        int f = 1;
        for (int i = 0; i < 128; ++i)
            if (obs32[2 * i + 1] != 0) { f = 0; break; }
        g_is64 = f;
    }
}

// ---------------- kernel 1: lse over V ----------------
__global__ void lse_kernel(const float* __restrict__ emis) {
    int row = blockIdx.x;
    const float4* x4 = (const float4*)(emis + (size_t)row * VV);
    int tid = threadIdx.x;
    __shared__ float sr[256];

    float m = -1e30f;
    for (int i = tid; i < VV / 4; i += 256) {
        float4 v = x4[i];
        m = fmaxf(m, fmaxf(fmaxf(v.x, v.y), fmaxf(v.z, v.w)));
    }
    sr[tid] = m; __syncthreads();
    for (int s = 128; s; s >>= 1) { if (tid < s) sr[tid] = fmaxf(sr[tid], sr[tid + s]); __syncthreads(); }
    m = sr[0]; __syncthreads();

    float sum = 0.f;
    for (int i = tid; i < VV / 4; i += 256) {
        float4 v = x4[i];
        sum += expf(v.x - m) + expf(v.y - m) + expf(v.z - m) + expf(v.w - m);
    }
    sr[tid] = sum; __syncthreads();
    for (int s = 128; s; s >>= 1) { if (tid < s) sr[tid] += sr[tid + s]; __syncthreads(); }
    if (tid == 0) g_lse[row] = m + logf(sr[0]);
}

// ---------------- kernel 2: transpose with lse subtract ----------------
__global__ void transpose_kernel(const float* __restrict__ emis) {
    __shared__ float tile[32][33];
    int s  = blockIdx.z;
    int v0 = blockIdx.x * 32;
    int h0 = blockIdx.y * 32;
    int tx = threadIdx.x, ty = threadIdx.y;

    #pragma unroll
    for (int r = 0; r < 4; ++r) {
        int h = h0 + ty + 8 * r;
        int v = v0 + tx;
        float val = 0.f;
        if (v < VV) val = emis[((size_t)s * HH + h) * VV + v] - g_lse[s * HH + h];
        tile[ty + 8 * r][tx] = val;
    }
    __syncthreads();
    #pragma unroll
    for (int r = 0; r < 4; ++r) {
        int v = v0 + ty + 8 * r;
        int h = h0 + tx;
        if (v < VV) g_leT[((size_t)s * VV + v) * HH + h] = tile[tx][ty + 8 * r];
    }
}

// ---------------- kernel 3: mixed-format P + row-sum corr ----------------
// rows with (j&128)==0 -> half(P); rows with (j&128)!=0 -> e4m3(P*256)
__global__ void psoftmax_kernel(const float* __restrict__ tran) {
    int j = blockIdx.x;
    const float* row = tran + (size_t)j * HH;
    int tid = threadIdx.x;
    __shared__ float sr[256];

    float a = row[tid], b = row[tid + 256];
    sr[tid] = fmaxf(a, b); __syncthreads();
    for (int s = 128; s; s >>= 1) { if (tid < s) sr[tid] = fmaxf(sr[tid], sr[tid + s]); __syncthreads(); }
    float m = sr[0]; __syncthreads();

    float ea = expf(a - m), eb = expf(b - m);
    sr[tid] = ea + eb; __syncthreads();
    for (int s = 128; s; s >>= 1) { if (tid < s) sr[tid] += sr[tid + s]; __syncthreads(); }
    float sum = sr[0];
    __syncthreads();

    bool rhalf = (j & 128) == 0;
    float da;
    if (rhalf) {
        float inv = 1.0f / sum;
        __half qa = __float2half_rn(ea * inv);
        __half qb = __float2half_rn(eb * inv);
        g_Ph[(size_t)j * HH + tid]       = qa;
        g_Ph[(size_t)j * HH + tid + 256] = qb;
        da = __half2float(qa) + __half2float(qb);
    } else {
        float inv = 256.0f / sum;
        __nv_fp8_storage_t qa = __nv_cvt_float_to_fp8(ea * inv, __NV_SATFINITE, __NV_E4M3);
        __nv_fp8_storage_t qb = __nv_cvt_float_to_fp8(eb * inv, __NV_SATFINITE, __NV_E4M3);
        g_P8[(size_t)j * HH + tid]       = qa;
        g_P8[(size_t)j * HH + tid + 256] = qb;
        __half_raw ha = __nv_cvt_fp8_to_halfraw(qa, __NV_E4M3);
        __half_raw hb = __nv_cvt_fp8_to_halfraw(qb, __NV_E4M3);
        da = __half2float(*(__half*)&ha) + __half2float(*(__half*)&hb);
    }
    sr[tid] = da; __syncthreads();
    for (int s = 128; s; s >>= 1) { if (tid < s) sr[tid] += sr[tid + s]; __syncthreads(); }
    if (tid == 0) g_corr[j] = (rhalf ? 1.0f : 256.0f) / sr[0];
}

// ---------------- kernel 4: gather em, smax & E ----------------
__global__ void emE_kernel(const void* __restrict__ obs_raw,
                           const float* __restrict__ priors) {
    int t = blockIdx.x, b = blockIdx.y;
    int tid = threadIdx.x;
    int lane = tid & 31, wid = tid >> 5;
    __shared__ float sm[4];

    int o[SS];
    if (g_is64) {
        const long long* p = (const long long*)obs_raw + ((size_t)(b * TT + t)) * SS;
        #pragma unroll
        for (int s = 0; s < SS; ++s) o[s] = (int)p[s];
    } else {
        const int* p = (const int*)obs_raw + ((size_t)(b * TT + t)) * SS;
        #pragma unroll
        for (int s = 0; s < SS; ++s) o[s] = p[s];
    }

    float4 acc = make_float4(0.f, 0.f, 0.f, 0.f);
    #pragma unroll
    for (int s = 0; s < SS; ++s) {
        const float4* r = (const float4*)(g_leT + ((size_t)s * VV + o[s]) * HH);
        float4 v = r[tid];
        acc.x += v.x; acc.y += v.y; acc.z += v.z; acc.w += v.w;
    }
    acc.x *= 0.25f; acc.y *= 0.25f; acc.z *= 0.25f; acc.w *= 0.25f;

    if (t == 0) {
        float4 pr = ((const float4*)priors)[tid];
        acc.x += pr.x; acc.y += pr.y; acc.z += pr.z; acc.w += pr.w;
    }

    float m = fmaxf(fmaxf(acc.x, acc.y), fmaxf(acc.z, acc.w));
    m = warp_max(m);
    if (lane == 0) sm[wid] = m;
    __syncthreads();
    m = fmaxf(fmaxf(sm[0], sm[1]), fmaxf(sm[2], sm[3]));

    float4 e;
    e.x = __expf(acc.x - m); e.y = __expf(acc.y - m);
    e.z = __expf(acc.z - m); e.w = __expf(acc.w - m);
    ((float4*)(g_E + ((size_t)(b * TT + t)) * HH))[tid] = e;
    if (tid == 0) g_smax[b * TT + t] = m;
}

// ---------------- kernel 5: forward recursion, 2-CTA cluster per batch ----------------
// smem layout (bytes)
#define SM_PHALF 0            // 128 rows x 512 half = 131072
#define SM_P8    131072       // 128 rows x 512 fp8  = 65536
#define SM_PART  196608       // 8 x 512 floats = 16384
#define SM_PVEC  212992       // 256 x u32 (half2 bcast p) = 1024
#define SM_RECV  214016       // 2 x 256 floats = 2048 (double buffer)
#define SM_RED   216064       // 16 floats (+pad)
#define SM_BC    216128       // float
#define SM_SRECV 216136       // 2 floats (double buffer)
#define SM_MBAR  216144       // 8B
#define SMEM_TOTAL 216192

__global__ void __launch_bounds__(512, 1) __cluster_dims__(2, 1, 1)
forward_kernel(const void* __restrict__ lengths_raw, float* __restrict__ out) {
    extern __shared__ char sm[];
    const int tid  = threadIdx.x;
    const int b    = blockIdx.x >> 1;
    const unsigned rank = blockIdx.x & 1;
    const unsigned peer = rank ^ 1;
    const int lane = tid & 31, wid = tid >> 5;
    const bool own = ((unsigned)(tid >> 8) == rank);     // global k = tid is mine
    const bool leader = (tid == (int)(rank << 8));       // one own-half thread
    const int u = tid & 255;

    const uint32_t sbase = smem_u32(sm);
    const uint32_t mbarP = sbase + SM_MBAR;
    float*    part  = (float*)(sm + SM_PART);
    unsigned* p_h   = (unsigned*)(sm + SM_PVEC);
    float*    recv  = (float*)(sm + SM_RECV);
    float*    red   = (float*)(sm + SM_RED);
    float*    bc    = (float*)(sm + SM_BC);
    float*    srecv = (float*)(sm + SM_SRECV);

    if (tid == 0) {
        mbar_init(mbarP, 257);
        bc[0] = 0.f; srecv[0] = 0.f; srecv[1] = 0.f;
    }
    if (tid < 512) { ((float*)(sm + SM_RECV))[tid] = 0.f; }

    // load P slices: local rows [0,128) as half from global rows rank*256+[0,128),
    //                local rows [128,256) as fp8 from global rows rank*256+[128,256)
    {
        const uint4* src_h = (const uint4*)(g_Ph + (size_t)(rank * HALFH) * HH);
        uint4* dst_h = (uint4*)(sm + SM_PHALF);
        #pragma unroll
        for (int r = 0; r < 16; ++r) dst_h[tid + 512 * r] = src_h[tid + 512 * r];   // 8192 uint4
        const uint4* src_8 = (const uint4*)(g_P8 + (size_t)(rank * HALFH + 128) * HH);
        uint4* dst_8 = (uint4*)(sm + SM_P8);
        #pragma unroll
        for (int r = 0; r < 8; ++r) dst_8[tid + 512 * r] = src_8[tid + 512 * r];    // 4096 uint4
    }
    const float corrk = g_corr[tid];   // correction for row j = tid (used when writing p[tid])
    __syncthreads();
    CLUSTER_SYNC_();

    const int len = g_is64 ? (int)((const long long*)lengths_raw)[b]
                           : ((const int*)lengths_raw)[b];
    const float* Eb  = g_E + (size_t)b * TT * HH;
    const float* smx = g_smax + (size_t)b * TT;

    // matvec mapping: 8 groups of 64 threads; group g -> local rows [g*32, g*32+32),
    // thread i in group owns k = 8i..8i+7. groups 0-3: half rows, 4-7: fp8 rows.
    const int g = tid >> 6, i = tid & 63;
    const bool ghalf = (g < 4);
    const uint4* PH4 = (const uint4*)(sm + SM_PHALF) + (size_t)(g * 32) * 64 + i;
    const uint2* P2  = (const uint2*)(sm + SM_P8)    + (size_t)((g - 4) * 32) * 64 + i;
    float*       prow = part + g * 512 + i * 8;
    const uint4* ph4  = (const uint4*)(sm + SM_PVEC) + g * 8;

    unsigned pp = 0;
    float c = 0.f;
    float e_cur = __ldg(Eb + tid);
    float smt_cur = leader ? __ldg(smx) : 0.f;

    for (int t = 0; t < len; ++t) {
        // prefetch next E row / smax (hidden under matvec)
        float e_next = 0.f, smt_next = 0.f;
        if (t + 1 < len) {
            e_next = __ldg(Eb + (size_t)(t + 1) * HH + tid);
            if (leader) smt_next = __ldg(smx + t + 1);
        }

        float w;
        if (t == 0) {
            w = own ? e_cur : 0.f;
        } else {
            unsigned prs[32];
            #pragma unroll
            for (int r = 0; r < 8; ++r) *(uint4*)&prs[4 * r] = ph4[r];

            __half2 a0 = __float2half2_rn(0.f), a1 = a0, a2 = a0, a3 = a0;
            if (ghalf) {
                #pragma unroll
                for (int jj = 0; jj < 32; ++jj) {
                    uint4 q = PH4[(size_t)jj * 64];
                    __half2 hp = u32_h2(prs[jj]);
                    a0 = __hfma2(hp, u32_h2(q.x), a0);   // (k0,k1)
                    a1 = __hfma2(hp, u32_h2(q.y), a1);   // (k2,k3)
                    a2 = __hfma2(hp, u32_h2(q.z), a2);   // (k4,k5)
                    a3 = __hfma2(hp, u32_h2(q.w), a3);   // (k6,k7)
                }
                float2 f0 = __half22float2(a0), f1 = __half22float2(a1);
                float2 f2 = __half22float2(a2), f3 = __half22float2(a3);
                *(float4*)prow       = make_float4(f0.x, f0.y, f1.x, f1.y);
                *(float4*)(prow + 4) = make_float4(f2.x, f2.y, f3.x, f3.y);
            } else {
                #pragma unroll
                for (int jj = 0; jj < 32; ++jj) {
                    uint2 q = P2[(size_t)jj * 64];
                    __half2 hp = u32_h2(prs[jj]);
                    a0 = __hfma2(hp, fp8lo(q.x), a0);    // (k0,k2)
                    a1 = __hfma2(hp, fp8hi(q.x), a1);    // (k1,k3)
                    a2 = __hfma2(hp, fp8lo(q.y), a2);    // (k4,k6)
                    a3 = __hfma2(hp, fp8hi(q.y), a3);    // (k5,k7)
                }
                float2 f0 = __half22float2(a0), f1 = __half22float2(a1);
                float2 f2 = __half22float2(a2), f3 = __half22float2(a3);
                *(float4*)prow       = make_float4(f0.x, f1.x, f0.y, f1.y);
                *(float4*)(prow + 4) = make_float4(f2.x, f3.x, f2.y, f3.y);
            }
            __syncthreads();

            float tot = 0.f;
            #pragma unroll
            for (int r = 0; r < 8; ++r) tot += part[r * 512 + tid];
            w = e_cur * tot;
        }

        // local scalar reduction (S_r) + single merged exchange phase
        float s1 = warp_sum(w);
        if (lane == 0) red[wid] = s1;
        if (!own) {
            st_remote_f32(sbase + SM_RECV + ((unsigned)(t & 1) << 10) + 4u * (unsigned)u, peer, w);
            mbar_arrive_remote(mbarP, peer);
        }
        __syncthreads();
        if (leader) {
            float Sr = 0.f;
            #pragma unroll
            for (int r = 0; r < 16; ++r) Sr += red[r];
            bc[0] = Sr;
            st_remote_f32(sbase + SM_SRECV + 4u * (unsigned)(t & 1), peer, Sr);
            mbar_arrive_remote(mbarP, peer);
        }
        mbar_wait(mbarP, pp); pp ^= 1;

        float S = bc[0] + srecv[t & 1];
        if (own) {
            float pk = (w + recv[((t & 1) << 8) + u]) * __frcp_rn(S) * corrk;
            unsigned hu = (unsigned)__half_as_ushort(__float2half_rn(pk));
            p_h[u] = hu | (hu << 16);
        }
        if (leader) c += smt_cur + __logf(S);
        e_cur = e_next; smt_cur = smt_next;
        __syncthreads();
    }

    if (leader && rank == 0) out[b] = c;
    CLUSTER_SYNC_();
}

// ---------------- launcher ----------------
extern "C" void kernel_launch(void* const* d_in, const int* in_sizes, int n_in,
                              void* d_out, int out_size) {
    const void*  obs     = d_in[0];
    const void*  lengths = d_in[1];
    const float* emis    = (const float*)d_in[2];
    const float* tran    = (const float*)d_in[3];
    const float* priors  = (const float*)d_in[4];
    float* out = (float*)d_out;

    cudaFuncSetAttribute(forward_kernel, cudaFuncAttributeMaxDynamicSharedMemorySize, SMEM_TOTAL);

    detect_kernel<<<1, 32>>>((const int*)obs);
    lse_kernel<<<SS * HH, 256>>>(emis);
    transpose_kernel<<<dim3((VV + 31) / 32, HH / 32, SS), dim3(32, 8)>>>(emis);
    psoftmax_kernel<<<HH, 256>>>(tran);
    emE_kernel<<<dim3(TT, BB), 128>>>(obs, priors);
    forward_kernel<<<BB * 2, 512, SMEM_TOTAL>>>(lengths, out);
}

// round 5
// speedup vs baseline: 1.1530x; 1.1530x over previous
#include <cuda_runtime.h>
#include <cuda_bf16.h>
#include <cuda_fp16.h>
#include <cuda_fp8.h>
#include <cstdint>

#define BB 64
#define TT 512
#define SS 4
#define HH 512
#define VV 10000
#define HALFH 256

// ---------------- device scratch ----------------
__device__ float g_lse[SS * HH];
__device__ float g_leT[(size_t)SS * VV * HH];          // [s][v][h]
__device__ float g_E[(size_t)BB * TT * HH];            // exp(em - smax)
__device__ float g_smax[BB * TT];
__device__ unsigned char g_P8[HH * HH];                // e4m3(P*256), row-major [j][k]
__device__ float g_corr[HH];                           // effective row-sum correction
__device__ int g_is64;

// ---------------- helpers ----------------
__device__ __forceinline__ float warp_sum(float v) {
    #pragma unroll
    for (int o = 16; o; o >>= 1) v += __shfl_xor_sync(0xffffffffu, v, o);
    return v;
}
__device__ __forceinline__ float warp_max(float v) {
    #pragma unroll
    for (int o = 16; o; o >>= 1) v = fmaxf(v, __shfl_xor_sync(0xffffffffu, v, o));
    return v;
}
__device__ __forceinline__ uint32_t smem_u32(const void* p) {
    uint32_t a;
    asm("{ .reg .u64 t; cvta.to.shared.u64 t, %1; cvt.u32.u64 %0, t; }" : "=r"(a) : "l"(p));
    return a;
}
__device__ __forceinline__ __half2 u32_h2(unsigned u) {
    __half2 h;
    *reinterpret_cast<unsigned*>(&h) = u;
    return h;
}
// sign-free e4m3 -> half via bit shift: value = e4m3 * 2^-8 exactly.
// P stored as e4m3(P*256) => dequant yields exactly ~P (corr fixes row sums).
__device__ __forceinline__ __half2 fp8lo(unsigned q) { return u32_h2((q & 0x00ff00ffu) << 7); }   // (b0,b2)
__device__ __forceinline__ __half2 fp8hi(unsigned q) { return u32_h2((q >> 1) & 0x7f807f80u); }   // (b1,b3)

__device__ __forceinline__ void mbar_init(uint32_t m, unsigned cnt) {
    asm volatile("mbarrier.init.shared.b64 [%0], %1;" :: "r"(m), "r"(cnt) : "memory");
}
__device__ __forceinline__ void mbar_arrive_remote(uint32_t m_local, unsigned peer) {
    asm volatile("{\n\t.reg .b32 r;\n\t"
                 "mapa.shared::cluster.u32 r, %0, %1;\n\t"
                 "mbarrier.arrive.release.cluster.shared::cluster.b64 _, [r];\n\t}"
                 :: "r"(m_local), "r"(peer) : "memory");
}
__device__ __forceinline__ void st_remote_f32(uint32_t a_local, unsigned peer, float v) {
    asm volatile("{\n\t.reg .b32 r;\n\t"
                 "mapa.shared::cluster.u32 r, %0, %1;\n\t"
                 "st.shared::cluster.f32 [r], %2;\n\t}"
                 :: "r"(a_local), "r"(peer), "f"(v) : "memory");
}
__device__ __forceinline__ void st_remote_u32(uint32_t a_local, unsigned peer, unsigned v) {
    asm volatile("{\n\t.reg .b32 r;\n\t"
                 "mapa.shared::cluster.u32 r, %0, %1;\n\t"
                 "st.shared::cluster.u32 [r], %2;\n\t}"
                 :: "r"(a_local), "r"(peer), "r"(v) : "memory");
}
__device__ __forceinline__ void mbar_wait(uint32_t m, unsigned parity) {
    asm volatile("{\n\t.reg .pred P;\n\t"
                 "WL_%=:\n\t"
                 "mbarrier.try_wait.parity.acquire.cluster.shared::cta.b64 P, [%0], %1, 0x989680;\n\t"
                 "@P bra WD_%=;\n\t"
                 "bra WL_%=;\n\t"
                 "WD_%=:\n\t}"
                 :: "r"(m), "r"(parity) : "memory");
}
#define CLUSTER_SYNC_() do { \
    asm volatile("barrier.cluster.arrive.aligned;" ::: "memory"); \
    asm volatile("barrier.cluster.wait.aligned;" ::: "memory"); } while (0)

// ---------------- kernel 0: detect int64 vs int32 ----------------
__global__ void detect_kernel(const int* obs32) {
    if (threadIdx.x == 0) {
        int f = 1;
        for (int i = 0; i < 128; ++i)
            if (obs32[2 * i + 1] != 0) { f = 0; break; }
        g_is64 = f;
    }
}

// ---------------- kernel 1: lse over V ----------------
__global__ void lse_kernel(const float* __restrict__ emis) {
    int row = blockIdx.x;
    const float4* x4 = (const float4*)(emis + (size_t)row * VV);
    int tid = threadIdx.x;
    __shared__ float sr[256];

    float m = -1e30f;
    for (int i = tid; i < VV / 4; i += 256) {
        float4 v = x4[i];
        m = fmaxf(m, fmaxf(fmaxf(v.x, v.y), fmaxf(v.z, v.w)));
    }
    sr[tid] = m; __syncthreads();
    for (int s = 128; s; s >>= 1) { if (tid < s) sr[tid] = fmaxf(sr[tid], sr[tid + s]); __syncthreads(); }
    m = sr[0]; __syncthreads();

    float sum = 0.f;
    for (int i = tid; i < VV / 4; i += 256) {
        float4 v = x4[i];
        sum += expf(v.x - m) + expf(v.y - m) + expf(v.z - m) + expf(v.w - m);
    }
    sr[tid] = sum; __syncthreads();
    for (int s = 128; s; s >>= 1) { if (tid < s) sr[tid] += sr[tid + s]; __syncthreads(); }
    if (tid == 0) g_lse[row] = m + logf(sr[0]);
}

// ---------------- kernel 2: transpose with lse subtract ----------------
__global__ void transpose_kernel(const float* __restrict__ emis) {
    __shared__ float tile[32][33];
    int s  = blockIdx.z;
    int v0 = blockIdx.x * 32;
    int h0 = blockIdx.y * 32;
    int tx = threadIdx.x, ty = threadIdx.y;

    #pragma unroll
    for (int r = 0; r < 4; ++r) {
        int h = h0 + ty + 8 * r;
        int v = v0 + tx;
        float val = 0.f;
        if (v < VV) val = emis[((size_t)s * HH + h) * VV + v] - g_lse[s * HH + h];
        tile[ty + 8 * r][tx] = val;
    }
    __syncthreads();
    #pragma unroll
    for (int r = 0; r < 4; ++r) {
        int v = v0 + ty + 8 * r;
        int h = h0 + tx;
        if (v < VV) g_leT[((size_t)s * VV + v) * HH + h] = tile[tx][ty + 8 * r];
    }
}

// ---------------- kernel 3: P8 = e4m3(softmax(tran)*256) + row-sum corr ----------------
__global__ void psoftmax_kernel(const float* __restrict__ tran) {
    int j = blockIdx.x;
    const float* row = tran + (size_t)j * HH;
    int tid = threadIdx.x;
    __shared__ float sr[256];

    float a = row[tid], b = row[tid + 256];
    sr[tid] = fmaxf(a, b); __syncthreads();
    for (int s = 128; s; s >>= 1) { if (tid < s) sr[tid] = fmaxf(sr[tid], sr[tid + s]); __syncthreads(); }
    float m = sr[0]; __syncthreads();

    float ea = expf(a - m), eb = expf(b - m);
    sr[tid] = ea + eb; __syncthreads();
    for (int s = 128; s; s >>= 1) { if (tid < s) sr[tid] += sr[tid + s]; __syncthreads(); }
    float inv = 256.0f / sr[0];
    __syncthreads();

    __nv_fp8_storage_t qa = __nv_cvt_float_to_fp8(ea * inv, __NV_SATFINITE, __NV_E4M3);
    __nv_fp8_storage_t qb = __nv_cvt_float_to_fp8(eb * inv, __NV_SATFINITE, __NV_E4M3);
    g_P8[(size_t)j * HH + tid]       = qa;
    g_P8[(size_t)j * HH + tid + 256] = qb;

    __half_raw ha = __nv_cvt_fp8_to_halfraw(qa, __NV_E4M3);
    __half_raw hb = __nv_cvt_fp8_to_halfraw(qb, __NV_E4M3);
    float da = __half2float(*(__half*)&ha) + __half2float(*(__half*)&hb);
    sr[tid] = da; __syncthreads();
    for (int s = 128; s; s >>= 1) { if (tid < s) sr[tid] += sr[tid + s]; __syncthreads(); }
    if (tid == 0) g_corr[j] = 256.0f / sr[0];
}

// ---------------- kernel 4: gather em, smax & E ----------------
__global__ void emE_kernel(const void* __restrict__ obs_raw,
                           const float* __restrict__ priors) {
    int t = blockIdx.x, b = blockIdx.y;
    int tid = threadIdx.x;
    int lane = tid & 31, wid = tid >> 5;
    __shared__ float sm[4];

    int o[SS];
    if (g_is64) {
        const long long* p = (const long long*)obs_raw + ((size_t)(b * TT + t)) * SS;
        #pragma unroll
        for (int s = 0; s < SS; ++s) o[s] = (int)p[s];
    } else {
        const int* p = (const int*)obs_raw + ((size_t)(b * TT + t)) * SS;
        #pragma unroll
        for (int s = 0; s < SS; ++s) o[s] = p[s];
    }

    float4 acc = make_float4(0.f, 0.f, 0.f, 0.f);
    #pragma unroll
    for (int s = 0; s < SS; ++s) {
        const float4* r = (const float4*)(g_leT + ((size_t)s * VV + o[s]) * HH);
        float4 v = r[tid];
        acc.x += v.x; acc.y += v.y; acc.z += v.z; acc.w += v.w;
    }
    acc.x *= 0.25f; acc.y *= 0.25f; acc.z *= 0.25f; acc.w *= 0.25f;

    if (t == 0) {
        float4 pr = ((const float4*)priors)[tid];
        acc.x += pr.x; acc.y += pr.y; acc.z += pr.z; acc.w += pr.w;
    }

    float m = fmaxf(fmaxf(acc.x, acc.y), fmaxf(acc.z, acc.w));
    m = warp_max(m);
    if (lane == 0) sm[wid] = m;
    __syncthreads();
    m = fmaxf(fmaxf(sm[0], sm[1]), fmaxf(sm[2], sm[3]));

    float4 e;
    e.x = __expf(acc.x - m); e.y = __expf(acc.y - m);
    e.z = __expf(acc.z - m); e.w = __expf(acc.w - m);
    ((float4*)(g_E + ((size_t)(b * TT + t)) * HH))[tid] = e;
    if (tid == 0) g_smax[b * TT + t] = m;
}

// ---------------- kernel 5: forward, column-split 2-CTA cluster per batch ----------------
// Each CTA owns 256 output columns k (k-half = rank). Holds P[0..512)[my k-half] fp8.
// smem layout (bytes)
#define SM_P     0            // 512 rows x 256 fp8 = 131072
#define SM_PART  131072       // 8 x 256 floats = 8192
#define SM_PH    139264       // 256 u32 (half2 bcast p, my half) = 1024
#define SM_PRECV 140288       // 2 x 256 u32 (peer p, double buffered) = 2048
#define SM_RED   142336       // 8 floats
#define SM_RRECV 142368       // 2 x 8 floats (peer warp partial sums)
#define SM_MBARP 142432       // 8B (256 arrivals: peer p)
#define SM_MBARS 142440       // 8B (8 arrivals: peer S partials)
#define SMEM_TOTAL 142464

__global__ void __launch_bounds__(512, 1) __cluster_dims__(2, 1, 1)
forward_kernel(const void* __restrict__ lengths_raw, float* __restrict__ out) {
    extern __shared__ char sm[];
    const int tid  = threadIdx.x;
    const int b    = blockIdx.x >> 1;
    const unsigned rank = blockIdx.x & 1;
    const unsigned peer = rank ^ 1;
    const int lane = tid & 31, wid = tid >> 5;
    const bool reducer = (tid < 256);       // handles k = rank*256 + tid

    const uint32_t sbase = smem_u32(sm);
    const uint32_t mbarP = sbase + SM_MBARP;
    const uint32_t mbarS = sbase + SM_MBARS;
    float*    part  = (float*)(sm + SM_PART);
    unsigned* p_h   = (unsigned*)(sm + SM_PH);
    unsigned* precv = (unsigned*)(sm + SM_PRECV);
    float*    red   = (float*)(sm + SM_RED);
    float*    rrecv = (float*)(sm + SM_RRECV);

    if (tid == 0) {
        mbar_init(mbarP, 256);
        mbar_init(mbarS, 8);
    }

    // load P column slice: all 512 rows, my 256 k's (256B per row)
    {
        const uint4* src = (const uint4*)g_P8;   // row stride = 32 uint4
        uint4* dst = (uint4*)(sm + SM_P);
        #pragma unroll
        for (int r = 0; r < 16; ++r) {
            int idx = tid + 512 * r;
            int row = idx >> 4, c = idx & 15;
            dst[idx] = src[row * 32 + (int)rank * 16 + c];
        }
    }
    const float corrk = g_corr[rank * HALFH + (tid & 255)];
    __syncthreads();
    CLUSTER_SYNC_();

    const int len = g_is64 ? (int)((const long long*)lengths_raw)[b]
                           : ((const int*)lengths_raw)[b];
    const float* Eb  = g_E + (size_t)b * TT * HH + rank * HALFH;
    const float* smx = g_smax + (size_t)b * TT;

    unsigned pp = 0, psar = 0;
    float c = 0.f;

    float e_cur = reducer ? __ldg(Eb + tid) : 0.f;
    float smt_cur = (tid == 0) ? __ldg(smx) : 0.f;

    // matvec mapping: 8 groups of 64 threads; group handles 64 j-rows
    // (32 own-j + 32 peer-j); thread i owns k-local = 4i..4i+3.
    const int g = tid >> 6, i = tid & 63;
    const unsigned* ProwA = (const unsigned*)(sm + SM_P) + (size_t)(rank * HALFH + g * 32) * 64 + i;
    const unsigned* ProwB = (const unsigned*)(sm + SM_P) + (size_t)(peer * HALFH + g * 32) * 64 + i;
    const uint4* phA = (const uint4*)(sm + SM_PH) + g * 8;

    for (int t = 0; t < len; ++t) {
        const int bufR = (t - 1) & 1, bufW = t & 1;

        // prefetch next E/smax
        float e_next = 0.f, smt_next = 0.f;
        if (t + 1 < len) {
            if (reducer) e_next = __ldg(Eb + (size_t)(t + 1) * HH + tid);
            if (tid == 0) smt_next = __ldg(smx + t + 1);
        }

        float w = 0.f;
        if (t == 0) {
            if (reducer) w = e_cur;
        } else {
            // chunk A: own-j rows (p local)
            unsigned prs[32];
            #pragma unroll
            for (int r = 0; r < 8; ++r) *(uint4*)&prs[4 * r] = phA[r];
            __half2 a0 = __float2half2_rn(0.f), a1 = a0;
            #pragma unroll
            for (int jj = 0; jj < 32; ++jj) {
                unsigned q = ProwA[(size_t)jj * 64];
                __half2 hp = u32_h2(prs[jj]);
                a0 = __hfma2(hp, fp8lo(q), a0);   // (k0,k2)
                a1 = __hfma2(hp, fp8hi(q), a1);   // (k1,k3)
            }

            // wait for peer p (shipped end of t-1; hidden under chunk A)
            mbar_wait(mbarP, pp); pp ^= 1;

            // chunk B: peer-j rows (p from precv)
            const uint4* phB = (const uint4*)(precv + (size_t)bufR * 256) + g * 8;
            #pragma unroll
            for (int r = 0; r < 8; ++r) *(uint4*)&prs[4 * r] = phB[r];
            #pragma unroll
            for (int jj = 0; jj < 32; ++jj) {
                unsigned q = ProwB[(size_t)jj * 64];
                __half2 hp = u32_h2(prs[jj]);
                a0 = __hfma2(hp, fp8lo(q), a0);
                a1 = __hfma2(hp, fp8hi(q), a1);
            }

            float2 f0 = __half22float2(a0), f1 = __half22float2(a1);
            *(float4*)(part + g * 256 + i * 4) = make_float4(f0.x, f1.x, f0.y, f1.y);
            __syncthreads();

            if (reducer) {
                float tot = 0.f;
                #pragma unroll
                for (int r = 0; r < 8; ++r) tot += part[r * 256 + tid];
                w = e_cur * tot;
            }
        }

        if (reducer) {
            // per-warp partials: write local + ship remote immediately
            float s1 = warp_sum(w);
            if (lane == 0) {
                red[wid] = s1;
                st_remote_f32(sbase + SM_RRECV + ((unsigned)bufW << 5) + 4u * (unsigned)wid, peer, s1);
                mbar_arrive_remote(mbarS, peer);
            }
            asm volatile("bar.sync 1, 256;" ::: "memory");
            float S = red[0] + red[1] + red[2] + red[3] + red[4] + red[5] + red[6] + red[7];
            mbar_wait(mbarS, psar); psar ^= 1;
            const float* rr = rrecv + bufW * 8;
            S += rr[0] + rr[1] + rr[2] + rr[3] + rr[4] + rr[5] + rr[6] + rr[7];

            float pk = w * __frcp_rn(S) * corrk;
            unsigned hu = (unsigned)__half_as_ushort(__float2half_rn(pk));
            hu |= hu << 16;
            p_h[tid] = hu;
            st_remote_u32(sbase + SM_PRECV + ((unsigned)bufW << 10) + 4u * (unsigned)tid, peer, hu);
            mbar_arrive_remote(mbarP, peer);

            if (tid == 0) c += smt_cur + __logf(S);
        }
        e_cur = e_next; smt_cur = smt_next;
        __syncthreads();
    }

    if (tid == 0 && rank == 0) out[b] = c;
    CLUSTER_SYNC_();
}

// ---------------- launcher ----------------
extern "C" void kernel_launch(void* const* d_in, const int* in_sizes, int n_in,
                              void* d_out, int out_size) {
    const void*  obs     = d_in[0];
    const void*  lengths = d_in[1];
    const float* emis    = (const float*)d_in[2];
    const float* tran    = (const float*)d_in[3];
    const float* priors  = (const float*)d_in[4];
    float* out = (float*)d_out;

    cudaFuncSetAttribute(forward_kernel, cudaFuncAttributeMaxDynamicSharedMemorySize, SMEM_TOTAL);

    detect_kernel<<<1, 32>>>((const int*)obs);
    lse_kernel<<<SS * HH, 256>>>(emis);
    transpose_kernel<<<dim3((VV + 31) / 32, HH / 32, SS), dim3(32, 8)>>>(emis);
    psoftmax_kernel<<<HH, 256>>>(tran);
    emE_kernel<<<dim3(TT, BB), 128>>>(obs, priors);
    forward_kernel<<<BB * 2, 512, SMEM_TOTAL>>>(lengths, out);
}